// round 12
// baseline (speedup 1.0000x reference)
#include <cuda_runtime.h>
#include <cuda_fp16.h>
#include <math.h>
#include <stdint.h>

// Problem constants
#define Bb 4
#define Tt 2048
#define Dd 2048
#define Hh 16
#define Gg 4
#define Kk 128
#define Rr 4          // H / G
#define EPS 1e-6f
#define ROPE_BASE 10000.0f
#define SOFTMAX_SCALE 0.08838834764831845f  // K^-0.5

#define MTOT (Bb * Tt)          // 8192 rows

// --------------------------- scratch (device globals; no mallocs) ------------
__device__ float  g_q[(size_t)MTOT * Hh * Kk];     // 64 MB (pre-norm q, f32)
__device__ float  g_k[(size_t)MTOT * Gg * Kk];     // 16 MB (pre-norm k, f32)
__device__ int    g_pos[MTOT];
__device__ __half g_h16[(size_t)MTOT * Dd];        // 32 MB
__device__ __half g_wq16[(size_t)Dd * Hh * Kk];
__device__ __half g_wk16[(size_t)Dd * Gg * Kk];
__device__ __half g_wv16[(size_t)Dd * Gg * Kk];
__device__ __half g_wo16[(size_t)Hh * Kk * Dd];
__device__ __half g_q16[(size_t)MTOT * Hh * Kk];   // 32 MB (post norm+rope, *scale)
__device__ __half g_k16[(size_t)MTOT * Gg * Kk];   // 8 MB
__device__ __half g_v16[(size_t)MTOT * Gg * Kk];   // 8 MB (direct hgemm output)
__device__ __half g_a16[(size_t)MTOT * Hh * Kk];   // 32 MB (attn out, half)

#define MMA_F16(acc, af, b0v, b1v)                                             \
    asm volatile(                                                              \
        "mma.sync.aligned.m16n8k16.row.col.f32.f16.f16.f32 "                   \
        "{%0,%1,%2,%3}, {%4,%5,%6,%7}, {%8,%9}, {%0,%1,%2,%3};\n"              \
        : "+f"((acc)[0]), "+f"((acc)[1]), "+f"((acc)[2]), "+f"((acc)[3])       \
        : "r"((af)[0]), "r"((af)[1]), "r"((af)[2]), "r"((af)[3]),              \
          "r"(b0v), "r"(b1v))

__device__ __forceinline__ uint32_t h2u(__half2 h) { return *(uint32_t*)&h; }

// --------------------------- f32 -> f16 convert ------------------------------
__global__ __launch_bounds__(256)
void f2h_kernel(const float* __restrict__ src, __half* __restrict__ dst, int n) {
    int i = (blockIdx.x * blockDim.x + threadIdx.x) * 8;
    if (i >= n) return;
    float4 x = *(const float4*)(src + i);
    float4 y = *(const float4*)(src + i + 4);
    __half2 h0 = __floats2half2_rn(x.x, x.y);
    __half2 h1 = __floats2half2_rn(x.z, x.w);
    __half2 h2 = __floats2half2_rn(y.x, y.y);
    __half2 h3 = __floats2half2_rn(y.z, y.w);
    uint4 o;
    o.x = h2u(h0); o.y = h2u(h1); o.z = h2u(h2); o.w = h2u(h3);
    *(uint4*)(dst + i) = o;
}

// =============================================================================
// FP16 tensor-core GEMM:  C[M,N] = A[M,Kd](f16) @ B[Kd,N](f16), OutT f32/f16
// =============================================================================
#define HA_STR 40
#define HB_STR 136

template <typename OutT>
__global__ __launch_bounds__(256)
void hgemm_kernel(int M, int N, int Kd,
                  const __half* __restrict__ A,
                  const __half* __restrict__ B,
                  OutT* __restrict__ C) {
    __shared__ __half As[2][128][HA_STR];
    __shared__ __half Bs[2][32][HB_STR];

    const int tid  = threadIdx.x;
    const int lane = tid & 31;
    const int wid  = tid >> 5;
    const int warpM = wid & 1;
    const int warpN = wid >> 1;

    const __half* Ag = A + (size_t)blockIdx.y * 128 * Kd;
    const __half* Bg = B + (size_t)blockIdx.x * 128;

    float acc[4][4][4];
#pragma unroll
    for (int i = 0; i < 4; i++)
#pragma unroll
        for (int j = 0; j < 4; j++)
#pragma unroll
            for (int r = 0; r < 4; r++) acc[i][j][r] = 0.f;

    auto issue_loads = [&](int buf, int k0) {
#pragma unroll
        for (int i = 0; i < 2; i++) {
            int idx = tid + i * 256;
            int r = idx >> 2, c = (idx & 3) * 8;
            uint32_t dst = (uint32_t)__cvta_generic_to_shared(&As[buf][r][c]);
            const __half* src = Ag + (size_t)r * Kd + k0 + c;
            asm volatile("cp.async.cg.shared.global [%0], [%1], 16;\n"
                         :: "r"(dst), "l"(src));
        }
#pragma unroll
        for (int i = 0; i < 2; i++) {
            int idx = tid + i * 256;
            int r = idx >> 4, c = (idx & 15) * 8;
            uint32_t dst = (uint32_t)__cvta_generic_to_shared(&Bs[buf][r][c]);
            const __half* src = Bg + (size_t)(k0 + r) * N + c;
            asm volatile("cp.async.cg.shared.global [%0], [%1], 16;\n"
                         :: "r"(dst), "l"(src));
        }
        asm volatile("cp.async.commit_group;\n");
    };

    issue_loads(0, 0);
    const int KT = Kd >> 5;
    const int fr = lane >> 2;
    const int fc = lane & 3;
    const int grp = lane >> 3;
    const int gr8 = lane & 7;

    for (int kt = 0; kt < KT; kt++) {
        asm volatile("cp.async.wait_group 0;\n");
        __syncthreads();
        const int cur = kt & 1;
        if (kt + 1 < KT) issue_loads(cur ^ 1, (kt + 1) << 5);

#pragma unroll
        for (int kc = 0; kc < 2; kc++) {
            uint32_t af[4][4];
            uint32_t bf[4][2];
#pragma unroll
            for (int mt = 0; mt < 4; mt++) {
                int row = warpM * 64 + mt * 16 + (grp & 1) * 8 + gr8;
                int col = kc * 16 + (grp >> 1) * 8;
                uint32_t addr = (uint32_t)__cvta_generic_to_shared(&As[cur][row][col]);
                asm volatile("ldmatrix.sync.aligned.m8n8.x4.shared.b16 "
                             "{%0,%1,%2,%3}, [%4];\n"
                             : "=r"(af[mt][0]), "=r"(af[mt][1]),
                               "=r"(af[mt][2]), "=r"(af[mt][3])
                             : "r"(addr));
            }
#pragma unroll
            for (int np = 0; np < 2; np++) {
                int krow = kc * 16 + (grp & 1) * 8 + gr8;
                int ncol = warpN * 32 + np * 16 + (grp >> 1) * 8;
                uint32_t addr = (uint32_t)__cvta_generic_to_shared(&Bs[cur][krow][ncol]);
                asm volatile("ldmatrix.sync.aligned.m8n8.x4.trans.shared.b16 "
                             "{%0,%1,%2,%3}, [%4];\n"
                             : "=r"(bf[np * 2][0]), "=r"(bf[np * 2][1]),
                               "=r"(bf[np * 2 + 1][0]), "=r"(bf[np * 2 + 1][1])
                             : "r"(addr));
            }
#pragma unroll
            for (int mt = 0; mt < 4; mt++)
#pragma unroll
                for (int nt = 0; nt < 4; nt++)
                    MMA_F16(acc[mt][nt], af[mt], bf[nt][0], bf[nt][1]);
        }
        __syncthreads();
    }

    OutT* Cg = C + (size_t)blockIdx.y * 128 * N + (size_t)blockIdx.x * 128;
#pragma unroll
    for (int mt = 0; mt < 4; mt++) {
#pragma unroll
        for (int nt = 0; nt < 4; nt++) {
            int row = warpM * 64 + mt * 16 + fr;
            int col = warpN * 32 + nt * 8 + fc * 2;
            if constexpr (sizeof(OutT) == 4) {
                *(float2*)((float*)Cg + (size_t)row * N + col) =
                    make_float2(acc[mt][nt][0], acc[mt][nt][1]);
                *(float2*)((float*)Cg + (size_t)(row + 8) * N + col) =
                    make_float2(acc[mt][nt][2], acc[mt][nt][3]);
            } else {
                *(uint32_t*)((__half*)Cg + (size_t)row * N + col) =
                    h2u(__floats2half2_rn(acc[mt][nt][0], acc[mt][nt][1]));
                *(uint32_t*)((__half*)Cg + (size_t)(row + 8) * N + col) =
                    h2u(__floats2half2_rn(acc[mt][nt][2], acc[mt][nt][3]));
            }
        }
    }
}

// --------------------------- positions from sorted segment ids ---------------
__global__ void pos_kernel(const int* __restrict__ seg, int* __restrict__ pos) {
    int idx = blockIdx.x * blockDim.x + threadIdx.x;
    if (idx >= MTOT) return;
    int b = idx / Tt;
    int t = idx % Tt;
    const int* row = seg + (size_t)b * Tt;
    int s = row[t];
    int lo = 0, hi = t;
    while (lo < hi) {
        int mid = (lo + hi) >> 1;
        if (row[mid] < s) lo = mid + 1; else hi = mid;
    }
    pos[idx] = t - lo;
}

// ---------------- fused RMSNorm + RoPE, f32 in -> f16 out --------------------
__global__ __launch_bounds__(128)
void rms_rope_kernel(const float* __restrict__ x, const float* __restrict__ scale,
                     const int* __restrict__ pos, __half* __restrict__ outh,
                     int NH, float post_mul) {
    const int bt = blockIdx.x / NH;
    const int h  = blockIdx.x % NH;
    const float* p = x + ((size_t)bt * NH + h) * Kk;
    __half* po = outh + ((size_t)bt * NH + h) * Kk;

    const int i = threadIdx.x;
    float v = p[i];

    __shared__ float red[4];
    __shared__ float sx[Kk];
    float sq = v * v;
#pragma unroll
    for (int o = 16; o; o >>= 1) sq += __shfl_xor_sync(0xffffffffu, sq, o);
    if ((i & 31) == 0) red[i >> 5] = sq;
    __syncthreads();
    float var = (red[0] + red[1] + red[2] + red[3]) * (1.0f / Kk);
    float xn  = v * rsqrtf(var + EPS) * scale[i];
    sx[i] = xn;
    __syncthreads();

    if (i < Kk / 2) {
        float x1 = sx[i];
        float x2 = sx[i + Kk / 2];
        float pp = (float)pos[bt];
        float inv = expf(-logf(ROPE_BASE) * (2.0f * (float)i / (float)Kk));
        float ang = pp * inv;
        float s, c;
        sincosf(ang, &s, &c);
        po[i]           = __float2half_rn((x1 * c - x2 * s) * post_mul);
        po[i + Kk / 2]  = __float2half_rn((x2 * c + x1 * s) * post_mul);
    }
}

// =============================================================================
// Flash attention, fp16 tensor cores (m16n8k16), P kept in registers.
// Block = (32-query tile, g, b); 8 warps; warp w: head w>>1, 16 query rows.
// q is pre-scaled by SOFTMAX_SCALE. Key window [t-pos[t], t].
// =============================================================================
#define KV_STR 136

__device__ __forceinline__ float qmax2(float x) {
    x = fmaxf(x, __shfl_xor_sync(0xffffffffu, x, 1));
    x = fmaxf(x, __shfl_xor_sync(0xffffffffu, x, 2));
    return x;
}
__device__ __forceinline__ float qsum2(float x) {
    x += __shfl_xor_sync(0xffffffffu, x, 1);
    x += __shfl_xor_sync(0xffffffffu, x, 2);
    return x;
}

__global__ __launch_bounds__(256)
void fa16_kernel(const __half* __restrict__ q, const __half* __restrict__ k,
                 const __half* __restrict__ v, const int* __restrict__ pos,
                 __half* __restrict__ out) {
    __shared__ __half Ks[2][32][KV_STR];
    __shared__ __half Vs[2][32][KV_STR];

    const int tid  = threadIdx.x;
    const int lane = tid & 31;
    const int w    = tid >> 5;
    const int t0   = blockIdx.x * 32;
    const int g    = blockIdx.y;
    const int b    = blockIdx.z;

    const int h_local = w >> 1;
    const int q_base  = (w & 1) * 16;
    const int h = g * Rr + h_local;

    const int fr = lane >> 2;
    const int fc = lane & 3;

    const int t_r0 = t0 + q_base + fr;
    const int t_r1 = t_r0 + 8;
    const int w0lo = t_r0 - pos[b * Tt + t_r0];
    const int w1lo = t_r1 - pos[b * Tt + t_r1];

    // Q fragments: 8 chunks of k16
    uint32_t qf[8][4];
    {
        const __half* q0p = q + (((size_t)b * Tt + t_r0) * Hh + h) * Kk;
        const __half* q1p = q + (((size_t)b * Tt + t_r1) * Hh + h) * Kk;
#pragma unroll
        for (int kc = 0; kc < 8; kc++) {
            qf[kc][0] = *(const uint32_t*)(q0p + kc * 16 + 2 * fc);
            qf[kc][1] = *(const uint32_t*)(q1p + kc * 16 + 2 * fc);
            qf[kc][2] = *(const uint32_t*)(q0p + kc * 16 + 8 + 2 * fc);
            qf[kc][3] = *(const uint32_t*)(q1p + kc * 16 + 8 + 2 * fc);
        }
    }

    float oa[16][4];
#pragma unroll
    for (int i = 0; i < 16; i++)
#pragma unroll
        for (int j = 0; j < 4; j++) oa[i][j] = 0.f;
    float m0 = -1e30f, m1 = -1e30f, l0 = 0.f, l1 = 0.f;

    const int s_begin = (t0 - pos[b * Tt + t0]) & ~31;
    const int n_tiles = ((t0 + 31 - s_begin) >> 5) + 1;

    const __half* kg = k + ((size_t)b * Tt * Gg + g) * Kk;
    const __half* vg = v + ((size_t)b * Tt * Gg + g) * Kk;

    auto load_tile = [&](int buf, int s_tile) {
#pragma unroll
        for (int i = 0; i < 2; i++) {
            int idx = tid + i * 256;
            int r = idx >> 4, c = (idx & 15) * 8;
            uint32_t dst = (uint32_t)__cvta_generic_to_shared(&Ks[buf][r][c]);
            const __half* src = kg + (size_t)(s_tile + r) * Gg * Kk + c;
            asm volatile("cp.async.cg.shared.global [%0], [%1], 16;\n"
                         :: "r"(dst), "l"(src));
        }
#pragma unroll
        for (int i = 0; i < 2; i++) {
            int idx = tid + i * 256;
            int r = idx >> 4, c = (idx & 15) * 8;
            uint32_t dst = (uint32_t)__cvta_generic_to_shared(&Vs[buf][r][c]);
            const __half* src = vg + (size_t)(s_tile + r) * Gg * Kk + c;
            asm volatile("cp.async.cg.shared.global [%0], [%1], 16;\n"
                         :: "r"(dst), "l"(src));
        }
        asm volatile("cp.async.commit_group;\n");
    };

    load_tile(0, s_begin);

    for (int it = 0; it < n_tiles; it++) {
        const int s_tile = s_begin + it * 32;
        asm volatile("cp.async.wait_group 0;\n");
        __syncthreads();
        const int cur = it & 1;
        if (it + 1 < n_tiles) load_tile(cur ^ 1, s_tile + 32);

        // ---- scores: S[16,32] = Q @ K^T (q pre-scaled) ----
        float sc[4][4];
#pragma unroll
        for (int nt = 0; nt < 4; nt++)
#pragma unroll
            for (int i = 0; i < 4; i++) sc[nt][i] = 0.f;

#pragma unroll
        for (int nt = 0; nt < 4; nt++) {
#pragma unroll
            for (int kcp = 0; kcp < 4; kcp++) {
                uint32_t r0, r1, r2, r3;
                uint32_t addr = (uint32_t)__cvta_generic_to_shared(
                    &Ks[cur][nt * 8 + (lane & 7)][kcp * 32 + 8 * (lane >> 3)]);
                asm volatile("ldmatrix.sync.aligned.m8n8.x4.shared.b16 "
                             "{%0,%1,%2,%3}, [%4];\n"
                             : "=r"(r0), "=r"(r1), "=r"(r2), "=r"(r3)
                             : "r"(addr));
                MMA_F16(sc[nt], qf[2 * kcp], r0, r1);
                MMA_F16(sc[nt], qf[2 * kcp + 1], r2, r3);
            }
        }

        // ---- mask + online softmax ----
        float x[4][4];
        float rm0 = -1e30f, rm1 = -1e30f;
#pragma unroll
        for (int nt = 0; nt < 4; nt++) {
            int s_b = s_tile + nt * 8 + fc * 2;
            x[nt][0] = (s_b     >= w0lo && s_b     <= t_r0) ? sc[nt][0] : -1e30f;
            x[nt][1] = (s_b + 1 >= w0lo && s_b + 1 <= t_r0) ? sc[nt][1] : -1e30f;
            x[nt][2] = (s_b     >= w1lo && s_b     <= t_r1) ? sc[nt][2] : -1e30f;
            x[nt][3] = (s_b + 1 >= w1lo && s_b + 1 <= t_r1) ? sc[nt][3] : -1e30f;
            rm0 = fmaxf(rm0, fmaxf(x[nt][0], x[nt][1]));
            rm1 = fmaxf(rm1, fmaxf(x[nt][2], x[nt][3]));
        }
        rm0 = qmax2(rm0);
        rm1 = qmax2(rm1);
        const float mn0 = fmaxf(m0, rm0);
        const float mn1 = fmaxf(m1, rm1);
        const float corr0 = __expf(m0 - mn0);
        const float corr1 = __expf(m1 - mn1);

        float e[4][4];
        float rs0 = 0.f, rs1 = 0.f;
#pragma unroll
        for (int nt = 0; nt < 4; nt++) {
            e[nt][0] = (x[nt][0] > -1e29f) ? __expf(x[nt][0] - mn0) : 0.f;
            e[nt][1] = (x[nt][1] > -1e29f) ? __expf(x[nt][1] - mn0) : 0.f;
            e[nt][2] = (x[nt][2] > -1e29f) ? __expf(x[nt][2] - mn1) : 0.f;
            e[nt][3] = (x[nt][3] > -1e29f) ? __expf(x[nt][3] - mn1) : 0.f;
            rs0 += e[nt][0] + e[nt][1];
            rs1 += e[nt][2] + e[nt][3];
        }
        l0 = l0 * corr0 + qsum2(rs0);
        l1 = l1 * corr1 + qsum2(rs1);
        m0 = mn0;
        m1 = mn1;

        // ---- pack P into A fragments (registers only) ----
        uint32_t pa[2][4];
#pragma unroll
        for (int kc2 = 0; kc2 < 2; kc2++) {
            pa[kc2][0] = h2u(__floats2half2_rn(e[2 * kc2][0],     e[2 * kc2][1]));
            pa[kc2][1] = h2u(__floats2half2_rn(e[2 * kc2][2],     e[2 * kc2][3]));
            pa[kc2][2] = h2u(__floats2half2_rn(e[2 * kc2 + 1][0], e[2 * kc2 + 1][1]));
            pa[kc2][3] = h2u(__floats2half2_rn(e[2 * kc2 + 1][2], e[2 * kc2 + 1][3]));
        }

#pragma unroll
        for (int nt = 0; nt < 16; nt++) {
            oa[nt][0] *= corr0;
            oa[nt][1] *= corr0;
            oa[nt][2] *= corr1;
            oa[nt][3] *= corr1;
        }

        // ---- O += P @ V ----
#pragma unroll
        for (int nt2 = 0; nt2 < 8; nt2++) {
#pragma unroll
            for (int kc2 = 0; kc2 < 2; kc2++) {
                uint32_t r0, r1, r2, r3;
                uint32_t addr = (uint32_t)__cvta_generic_to_shared(
                    &Vs[cur][kc2 * 16 + 8 * ((lane >> 3) & 1) + (lane & 7)]
                       [nt2 * 16 + 8 * (lane >> 4)]);
                asm volatile("ldmatrix.sync.aligned.m8n8.x4.trans.shared.b16 "
                             "{%0,%1,%2,%3}, [%4];\n"
                             : "=r"(r0), "=r"(r1), "=r"(r2), "=r"(r3)
                             : "r"(addr));
                MMA_F16(oa[2 * nt2], pa[kc2], r0, r1);
                MMA_F16(oa[2 * nt2 + 1], pa[kc2], r2, r3);
            }
        }
        __syncthreads();
    }

    // ---- epilogue: write half ----
    const float inv0 = 1.0f / l0;
    const float inv1 = 1.0f / l1;
    __half* o0 = out + (((size_t)b * Tt + t_r0) * Hh + h) * Kk;
    __half* o1 = out + (((size_t)b * Tt + t_r1) * Hh + h) * Kk;
#pragma unroll
    for (int nt = 0; nt < 16; nt++) {
        int d = nt * 8 + fc * 2;
        *(uint32_t*)(o0 + d) = h2u(__floats2half2_rn(oa[nt][0] * inv0, oa[nt][1] * inv0));
        *(uint32_t*)(o1 + d) = h2u(__floats2half2_rn(oa[nt][2] * inv1, oa[nt][3] * inv1));
    }
}

// --------------------------- launch --------------------------------------
extern "C" void kernel_launch(void* const* d_in, const int* in_sizes, int n_in,
                              void* d_out, int out_size) {
    const float* hidden  = (const float*)d_in[0];
    const float* wq      = (const float*)d_in[1];
    const float* wk      = (const float*)d_in[2];
    const float* wv      = (const float*)d_in[3];
    const float* wo      = (const float*)d_in[4];
    const float* q_scale = (const float*)d_in[5];
    const float* k_scale = (const float*)d_in[6];
    const int*   seg     = (const int*)d_in[7];
    float* out = (float*)d_out;

    float *qb, *kb;
    int* posb;
    __half *h16, *wq16, *wk16, *wv16, *wo16, *q16, *k16, *v16, *a16;
    cudaGetSymbolAddress((void**)&qb, g_q);
    cudaGetSymbolAddress((void**)&kb, g_k);
    cudaGetSymbolAddress((void**)&posb, g_pos);
    cudaGetSymbolAddress((void**)&h16, g_h16);
    cudaGetSymbolAddress((void**)&wq16, g_wq16);
    cudaGetSymbolAddress((void**)&wk16, g_wk16);
    cudaGetSymbolAddress((void**)&wv16, g_wv16);
    cudaGetSymbolAddress((void**)&wo16, g_wo16);
    cudaGetSymbolAddress((void**)&q16, g_q16);
    cudaGetSymbolAddress((void**)&k16, g_k16);
    cudaGetSymbolAddress((void**)&v16, g_v16);
    cudaGetSymbolAddress((void**)&a16, g_a16);

    // 0) convert inputs to fp16
    {
        int nh = MTOT * Dd;
        f2h_kernel<<<nh / (256 * 8), 256>>>(hidden, h16, nh);
        int nq = Dd * Hh * Kk;
        f2h_kernel<<<nq / (256 * 8), 256>>>(wq, wq16, nq);
        int nk = Dd * Gg * Kk;
        f2h_kernel<<<nk / (256 * 8), 256>>>(wk, wk16, nk);
        f2h_kernel<<<nk / (256 * 8), 256>>>(wv, wv16, nk);
        int no = Hh * Kk * Dd;
        f2h_kernel<<<no / (256 * 8), 256>>>(wo, wo16, no);
    }

    // 1) QKV projections
    {
        dim3 blk(256);
        dim3 grdQ((Hh * Kk) / 128, MTOT / 128);
        hgemm_kernel<float><<<grdQ, blk>>>(MTOT, Hh * Kk, Dd, h16, wq16, qb);
        dim3 grdK((Gg * Kk) / 128, MTOT / 128);
        hgemm_kernel<float><<<grdK, blk>>>(MTOT, Gg * Kk, Dd, h16, wk16, kb);
        hgemm_kernel<__half><<<grdK, blk>>>(MTOT, Gg * Kk, Dd, h16, wv16, v16);
    }

    // 2) positions
    pos_kernel<<<(MTOT + 255) / 256, 256>>>(seg, posb);

    // 3) RMSNorm + RoPE -> fp16 (q pre-scaled by softmax scale)
    rms_rope_kernel<<<MTOT * Hh, 128>>>(qb, q_scale, posb, q16, Hh, SOFTMAX_SCALE);
    rms_rope_kernel<<<MTOT * Gg, 128>>>(kb, k_scale, posb, k16, Gg, 1.0f);

    // 4) flash attention (fp16)
    {
        dim3 grd(Tt / 32, Gg, Bb);
        fa16_kernel<<<grd, 256>>>(q16, k16, v16, posb, a16);
    }

    // 5) output projection (f32 out)
    {
        dim3 blk(256);
        dim3 grd(Dd / 128, MTOT / 128);
        hgemm_kernel<float><<<grd, blk>>>(MTOT, Dd, Hh * Kk, a16, wo16, out);
    }
}

// round 13
// speedup vs baseline: 1.0029x; 1.0029x over previous
#include <cuda_runtime.h>
#include <cuda_fp16.h>
#include <math.h>
#include <stdint.h>

// Problem constants
#define Bb 4
#define Tt 2048
#define Dd 2048
#define Hh 16
#define Gg 4
#define Kk 128
#define Rr 4          // H / G
#define EPS 1e-6f
#define ROPE_BASE 10000.0f
#define SOFTMAX_SCALE 0.08838834764831845f  // K^-0.5

#define MTOT (Bb * Tt)          // 8192 rows

// --------------------------- scratch (device globals; no mallocs) ------------
__device__ float  g_q[(size_t)MTOT * Hh * Kk];     // 64 MB (pre-norm q, f32)
__device__ float  g_k[(size_t)MTOT * Gg * Kk];     // 16 MB (pre-norm k, f32)
__device__ int    g_pos[MTOT];
__device__ __half g_h16[(size_t)MTOT * Dd];        // 32 MB
__device__ __half g_wq16[(size_t)Dd * Hh * Kk];
__device__ __half g_wk16[(size_t)Dd * Gg * Kk];
__device__ __half g_wv16[(size_t)Dd * Gg * Kk];
__device__ __half g_wo16[(size_t)Hh * Kk * Dd];
__device__ __half g_q16[(size_t)MTOT * Hh * Kk];   // 32 MB (post norm+rope, *scale)
__device__ __half g_k16[(size_t)MTOT * Gg * Kk];   // 8 MB
__device__ __half g_v16[(size_t)MTOT * Gg * Kk];   // 8 MB (direct hgemm output)
__device__ __half g_a16[(size_t)MTOT * Hh * Kk];   // 32 MB (attn out, half)

#define MMA_F16(acc, af, b0v, b1v)                                             \
    asm volatile(                                                              \
        "mma.sync.aligned.m16n8k16.row.col.f32.f16.f16.f32 "                   \
        "{%0,%1,%2,%3}, {%4,%5,%6,%7}, {%8,%9}, {%0,%1,%2,%3};\n"              \
        : "+f"((acc)[0]), "+f"((acc)[1]), "+f"((acc)[2]), "+f"((acc)[3])       \
        : "r"((af)[0]), "r"((af)[1]), "r"((af)[2]), "r"((af)[3]),              \
          "r"(b0v), "r"(b1v))

__device__ __forceinline__ uint32_t h2u(__half2 h) { return *(uint32_t*)&h; }

// --------------------------- f32 -> f16 convert ------------------------------
__global__ __launch_bounds__(256)
void f2h_kernel(const float* __restrict__ src, __half* __restrict__ dst, int n) {
    int i = (blockIdx.x * blockDim.x + threadIdx.x) * 8;
    if (i >= n) return;
    float4 x = *(const float4*)(src + i);
    float4 y = *(const float4*)(src + i + 4);
    __half2 h0 = __floats2half2_rn(x.x, x.y);
    __half2 h1 = __floats2half2_rn(x.z, x.w);
    __half2 h2 = __floats2half2_rn(y.x, y.y);
    __half2 h3 = __floats2half2_rn(y.z, y.w);
    uint4 o;
    o.x = h2u(h0); o.y = h2u(h1); o.z = h2u(h2); o.w = h2u(h3);
    *(uint4*)(dst + i) = o;
}

// =============================================================================
// FP16 tensor-core GEMM:  C[M,N] = A[M,Kd](f16) @ B[Kd,N](f16), OutT f32/f16
// =============================================================================
#define HA_STR 40
#define HB_STR 136

template <typename OutT>
__global__ __launch_bounds__(256)
void hgemm_kernel(int M, int N, int Kd,
                  const __half* __restrict__ A,
                  const __half* __restrict__ B,
                  OutT* __restrict__ C) {
    __shared__ __half As[2][128][HA_STR];
    __shared__ __half Bs[2][32][HB_STR];

    const int tid  = threadIdx.x;
    const int lane = tid & 31;
    const int wid  = tid >> 5;
    const int warpM = wid & 1;
    const int warpN = wid >> 1;

    const __half* Ag = A + (size_t)blockIdx.y * 128 * Kd;
    const __half* Bg = B + (size_t)blockIdx.x * 128;

    float acc[4][4][4];
#pragma unroll
    for (int i = 0; i < 4; i++)
#pragma unroll
        for (int j = 0; j < 4; j++)
#pragma unroll
            for (int r = 0; r < 4; r++) acc[i][j][r] = 0.f;

    auto issue_loads = [&](int buf, int k0) {
#pragma unroll
        for (int i = 0; i < 2; i++) {
            int idx = tid + i * 256;
            int r = idx >> 2, c = (idx & 3) * 8;
            uint32_t dst = (uint32_t)__cvta_generic_to_shared(&As[buf][r][c]);
            const __half* src = Ag + (size_t)r * Kd + k0 + c;
            asm volatile("cp.async.cg.shared.global [%0], [%1], 16;\n"
                         :: "r"(dst), "l"(src));
        }
#pragma unroll
        for (int i = 0; i < 2; i++) {
            int idx = tid + i * 256;
            int r = idx >> 4, c = (idx & 15) * 8;
            uint32_t dst = (uint32_t)__cvta_generic_to_shared(&Bs[buf][r][c]);
            const __half* src = Bg + (size_t)(k0 + r) * N + c;
            asm volatile("cp.async.cg.shared.global [%0], [%1], 16;\n"
                         :: "r"(dst), "l"(src));
        }
        asm volatile("cp.async.commit_group;\n");
    };

    issue_loads(0, 0);
    const int KT = Kd >> 5;
    const int fr = lane >> 2;
    const int fc = lane & 3;
    const int grp = lane >> 3;
    const int gr8 = lane & 7;

    for (int kt = 0; kt < KT; kt++) {
        asm volatile("cp.async.wait_group 0;\n");
        __syncthreads();
        const int cur = kt & 1;
        if (kt + 1 < KT) issue_loads(cur ^ 1, (kt + 1) << 5);

#pragma unroll
        for (int kc = 0; kc < 2; kc++) {
            uint32_t af[4][4];
            uint32_t bf[4][2];
#pragma unroll
            for (int mt = 0; mt < 4; mt++) {
                int row = warpM * 64 + mt * 16 + (grp & 1) * 8 + gr8;
                int col = kc * 16 + (grp >> 1) * 8;
                uint32_t addr = (uint32_t)__cvta_generic_to_shared(&As[cur][row][col]);
                asm volatile("ldmatrix.sync.aligned.m8n8.x4.shared.b16 "
                             "{%0,%1,%2,%3}, [%4];\n"
                             : "=r"(af[mt][0]), "=r"(af[mt][1]),
                               "=r"(af[mt][2]), "=r"(af[mt][3])
                             : "r"(addr));
            }
#pragma unroll
            for (int np = 0; np < 2; np++) {
                int krow = kc * 16 + (grp & 1) * 8 + gr8;
                int ncol = warpN * 32 + np * 16 + (grp >> 1) * 8;
                uint32_t addr = (uint32_t)__cvta_generic_to_shared(&Bs[cur][krow][ncol]);
                asm volatile("ldmatrix.sync.aligned.m8n8.x4.trans.shared.b16 "
                             "{%0,%1,%2,%3}, [%4];\n"
                             : "=r"(bf[np * 2][0]), "=r"(bf[np * 2][1]),
                               "=r"(bf[np * 2 + 1][0]), "=r"(bf[np * 2 + 1][1])
                             : "r"(addr));
            }
#pragma unroll
            for (int mt = 0; mt < 4; mt++)
#pragma unroll
                for (int nt = 0; nt < 4; nt++)
                    MMA_F16(acc[mt][nt], af[mt], bf[nt][0], bf[nt][1]);
        }
        __syncthreads();
    }

    OutT* Cg = C + (size_t)blockIdx.y * 128 * N + (size_t)blockIdx.x * 128;
#pragma unroll
    for (int mt = 0; mt < 4; mt++) {
#pragma unroll
        for (int nt = 0; nt < 4; nt++) {
            int row = warpM * 64 + mt * 16 + fr;
            int col = warpN * 32 + nt * 8 + fc * 2;
            if constexpr (sizeof(OutT) == 4) {
                *(float2*)((float*)Cg + (size_t)row * N + col) =
                    make_float2(acc[mt][nt][0], acc[mt][nt][1]);
                *(float2*)((float*)Cg + (size_t)(row + 8) * N + col) =
                    make_float2(acc[mt][nt][2], acc[mt][nt][3]);
            } else {
                *(uint32_t*)((__half*)Cg + (size_t)row * N + col) =
                    h2u(__floats2half2_rn(acc[mt][nt][0], acc[mt][nt][1]));
                *(uint32_t*)((__half*)Cg + (size_t)(row + 8) * N + col) =
                    h2u(__floats2half2_rn(acc[mt][nt][2], acc[mt][nt][3]));
            }
        }
    }
}

// --------------------------- positions from sorted segment ids ---------------
__global__ void pos_kernel(const int* __restrict__ seg, int* __restrict__ pos) {
    int idx = blockIdx.x * blockDim.x + threadIdx.x;
    if (idx >= MTOT) return;
    int b = idx / Tt;
    int t = idx % Tt;
    const int* row = seg + (size_t)b * Tt;
    int s = row[t];
    int lo = 0, hi = t;
    while (lo < hi) {
        int mid = (lo + hi) >> 1;
        if (row[mid] < s) lo = mid + 1; else hi = mid;
    }
    pos[idx] = t - lo;
}

// ---------------- fused RMSNorm + RoPE, f32 in -> f16 out --------------------
__global__ __launch_bounds__(128)
void rms_rope_kernel(const float* __restrict__ x, const float* __restrict__ scale,
                     const int* __restrict__ pos, __half* __restrict__ outh,
                     int NH, float post_mul) {
    const int bt = blockIdx.x / NH;
    const int h  = blockIdx.x % NH;
    const float* p = x + ((size_t)bt * NH + h) * Kk;
    __half* po = outh + ((size_t)bt * NH + h) * Kk;

    const int i = threadIdx.x;
    float v = p[i];

    __shared__ float red[4];
    __shared__ float sx[Kk];
    float sq = v * v;
#pragma unroll
    for (int o = 16; o; o >>= 1) sq += __shfl_xor_sync(0xffffffffu, sq, o);
    if ((i & 31) == 0) red[i >> 5] = sq;
    __syncthreads();
    float var = (red[0] + red[1] + red[2] + red[3]) * (1.0f / Kk);
    float xn  = v * rsqrtf(var + EPS) * scale[i];
    sx[i] = xn;
    __syncthreads();

    if (i < Kk / 2) {
        float x1 = sx[i];
        float x2 = sx[i + Kk / 2];
        float pp = (float)pos[bt];
        float inv = expf(-logf(ROPE_BASE) * (2.0f * (float)i / (float)Kk));
        float ang = pp * inv;
        float s, c;
        sincosf(ang, &s, &c);
        po[i]           = __float2half_rn((x1 * c - x2 * s) * post_mul);
        po[i + Kk / 2]  = __float2half_rn((x2 * c + x1 * s) * post_mul);
    }
}

// =============================================================================
// Flash attention, fp16 tensor cores (m16n8k16), P kept in registers.
// Block = (32-query tile, g, b); 8 warps; warp w: head w>>1, 16 query rows.
// q is pre-scaled by SOFTMAX_SCALE. Key window [t-pos[t], t].
// =============================================================================
#define KV_STR 136

__device__ __forceinline__ float qmax2(float x) {
    x = fmaxf(x, __shfl_xor_sync(0xffffffffu, x, 1));
    x = fmaxf(x, __shfl_xor_sync(0xffffffffu, x, 2));
    return x;
}
__device__ __forceinline__ float qsum2(float x) {
    x += __shfl_xor_sync(0xffffffffu, x, 1);
    x += __shfl_xor_sync(0xffffffffu, x, 2);
    return x;
}

__global__ __launch_bounds__(256)
void fa16_kernel(const __half* __restrict__ q, const __half* __restrict__ k,
                 const __half* __restrict__ v, const int* __restrict__ pos,
                 __half* __restrict__ out) {
    __shared__ __half Ks[2][32][KV_STR];
    __shared__ __half Vs[2][32][KV_STR];

    const int tid  = threadIdx.x;
    const int lane = tid & 31;
    const int w    = tid >> 5;
    const int t0   = blockIdx.x * 32;
    const int g    = blockIdx.y;
    const int b    = blockIdx.z;

    const int h_local = w >> 1;
    const int q_base  = (w & 1) * 16;
    const int h = g * Rr + h_local;

    const int fr = lane >> 2;
    const int fc = lane & 3;

    const int t_r0 = t0 + q_base + fr;
    const int t_r1 = t_r0 + 8;
    const int w0lo = t_r0 - pos[b * Tt + t_r0];
    const int w1lo = t_r1 - pos[b * Tt + t_r1];

    // Q fragments: 8 chunks of k16
    uint32_t qf[8][4];
    {
        const __half* q0p = q + (((size_t)b * Tt + t_r0) * Hh + h) * Kk;
        const __half* q1p = q + (((size_t)b * Tt + t_r1) * Hh + h) * Kk;
#pragma unroll
        for (int kc = 0; kc < 8; kc++) {
            qf[kc][0] = *(const uint32_t*)(q0p + kc * 16 + 2 * fc);
            qf[kc][1] = *(const uint32_t*)(q1p + kc * 16 + 2 * fc);
            qf[kc][2] = *(const uint32_t*)(q0p + kc * 16 + 8 + 2 * fc);
            qf[kc][3] = *(const uint32_t*)(q1p + kc * 16 + 8 + 2 * fc);
        }
    }

    float oa[16][4];
#pragma unroll
    for (int i = 0; i < 16; i++)
#pragma unroll
        for (int j = 0; j < 4; j++) oa[i][j] = 0.f;
    float m0 = -1e30f, m1 = -1e30f, l0 = 0.f, l1 = 0.f;

    const int s_begin = (t0 - pos[b * Tt + t0]) & ~31;
    const int n_tiles = ((t0 + 31 - s_begin) >> 5) + 1;

    const __half* kg = k + ((size_t)b * Tt * Gg + g) * Kk;
    const __half* vg = v + ((size_t)b * Tt * Gg + g) * Kk;

    auto load_tile = [&](int buf, int s_tile) {
#pragma unroll
        for (int i = 0; i < 2; i++) {
            int idx = tid + i * 256;
            int r = idx >> 4, c = (idx & 15) * 8;
            uint32_t dst = (uint32_t)__cvta_generic_to_shared(&Ks[buf][r][c]);
            const __half* src = kg + (size_t)(s_tile + r) * Gg * Kk + c;
            asm volatile("cp.async.cg.shared.global [%0], [%1], 16;\n"
                         :: "r"(dst), "l"(src));
        }
#pragma unroll
        for (int i = 0; i < 2; i++) {
            int idx = tid + i * 256;
            int r = idx >> 4, c = (idx & 15) * 8;
            uint32_t dst = (uint32_t)__cvta_generic_to_shared(&Vs[buf][r][c]);
            const __half* src = vg + (size_t)(s_tile + r) * Gg * Kk + c;
            asm volatile("cp.async.cg.shared.global [%0], [%1], 16;\n"
                         :: "r"(dst), "l"(src));
        }
        asm volatile("cp.async.commit_group;\n");
    };

    load_tile(0, s_begin);

    for (int it = 0; it < n_tiles; it++) {
        const int s_tile = s_begin + it * 32;
        asm volatile("cp.async.wait_group 0;\n");
        __syncthreads();
        const int cur = it & 1;
        if (it + 1 < n_tiles) load_tile(cur ^ 1, s_tile + 32);

        // ---- scores: S[16,32] = Q @ K^T (q pre-scaled) ----
        float sc[4][4];
#pragma unroll
        for (int nt = 0; nt < 4; nt++)
#pragma unroll
            for (int i = 0; i < 4; i++) sc[nt][i] = 0.f;

#pragma unroll
        for (int nt = 0; nt < 4; nt++) {
#pragma unroll
            for (int kcp = 0; kcp < 4; kcp++) {
                uint32_t r0, r1, r2, r3;
                uint32_t addr = (uint32_t)__cvta_generic_to_shared(
                    &Ks[cur][nt * 8 + (lane & 7)][kcp * 32 + 8 * (lane >> 3)]);
                asm volatile("ldmatrix.sync.aligned.m8n8.x4.shared.b16 "
                             "{%0,%1,%2,%3}, [%4];\n"
                             : "=r"(r0), "=r"(r1), "=r"(r2), "=r"(r3)
                             : "r"(addr));
                MMA_F16(sc[nt], qf[2 * kcp], r0, r1);
                MMA_F16(sc[nt], qf[2 * kcp + 1], r2, r3);
            }
        }

        // ---- mask + online softmax ----
        float x[4][4];
        float rm0 = -1e30f, rm1 = -1e30f;
#pragma unroll
        for (int nt = 0; nt < 4; nt++) {
            int s_b = s_tile + nt * 8 + fc * 2;
            x[nt][0] = (s_b     >= w0lo && s_b     <= t_r0) ? sc[nt][0] : -1e30f;
            x[nt][1] = (s_b + 1 >= w0lo && s_b + 1 <= t_r0) ? sc[nt][1] : -1e30f;
            x[nt][2] = (s_b     >= w1lo && s_b     <= t_r1) ? sc[nt][2] : -1e30f;
            x[nt][3] = (s_b + 1 >= w1lo && s_b + 1 <= t_r1) ? sc[nt][3] : -1e30f;
            rm0 = fmaxf(rm0, fmaxf(x[nt][0], x[nt][1]));
            rm1 = fmaxf(rm1, fmaxf(x[nt][2], x[nt][3]));
        }
        rm0 = qmax2(rm0);
        rm1 = qmax2(rm1);
        const float mn0 = fmaxf(m0, rm0);
        const float mn1 = fmaxf(m1, rm1);
        const float corr0 = __expf(m0 - mn0);
        const float corr1 = __expf(m1 - mn1);

        float e[4][4];
        float rs0 = 0.f, rs1 = 0.f;
#pragma unroll
        for (int nt = 0; nt < 4; nt++) {
            e[nt][0] = (x[nt][0] > -1e29f) ? __expf(x[nt][0] - mn0) : 0.f;
            e[nt][1] = (x[nt][1] > -1e29f) ? __expf(x[nt][1] - mn0) : 0.f;
            e[nt][2] = (x[nt][2] > -1e29f) ? __expf(x[nt][2] - mn1) : 0.f;
            e[nt][3] = (x[nt][3] > -1e29f) ? __expf(x[nt][3] - mn1) : 0.f;
            rs0 += e[nt][0] + e[nt][1];
            rs1 += e[nt][2] + e[nt][3];
        }
        l0 = l0 * corr0 + qsum2(rs0);
        l1 = l1 * corr1 + qsum2(rs1);
        m0 = mn0;
        m1 = mn1;

        // ---- pack P into A fragments (registers only) ----
        uint32_t pa[2][4];
#pragma unroll
        for (int kc2 = 0; kc2 < 2; kc2++) {
            pa[kc2][0] = h2u(__floats2half2_rn(e[2 * kc2][0],     e[2 * kc2][1]));
            pa[kc2][1] = h2u(__floats2half2_rn(e[2 * kc2][2],     e[2 * kc2][3]));
            pa[kc2][2] = h2u(__floats2half2_rn(e[2 * kc2 + 1][0], e[2 * kc2 + 1][1]));
            pa[kc2][3] = h2u(__floats2half2_rn(e[2 * kc2 + 1][2], e[2 * kc2 + 1][3]));
        }

#pragma unroll
        for (int nt = 0; nt < 16; nt++) {
            oa[nt][0] *= corr0;
            oa[nt][1] *= corr0;
            oa[nt][2] *= corr1;
            oa[nt][3] *= corr1;
        }

        // ---- O += P @ V ----
#pragma unroll
        for (int nt2 = 0; nt2 < 8; nt2++) {
#pragma unroll
            for (int kc2 = 0; kc2 < 2; kc2++) {
                uint32_t r0, r1, r2, r3;
                uint32_t addr = (uint32_t)__cvta_generic_to_shared(
                    &Vs[cur][kc2 * 16 + 8 * ((lane >> 3) & 1) + (lane & 7)]
                       [nt2 * 16 + 8 * (lane >> 4)]);
                asm volatile("ldmatrix.sync.aligned.m8n8.x4.trans.shared.b16 "
                             "{%0,%1,%2,%3}, [%4];\n"
                             : "=r"(r0), "=r"(r1), "=r"(r2), "=r"(r3)
                             : "r"(addr));
                MMA_F16(oa[2 * nt2], pa[kc2], r0, r1);
                MMA_F16(oa[2 * nt2 + 1], pa[kc2], r2, r3);
            }
        }
        __syncthreads();
    }

    // ---- epilogue: write half ----
    const float inv0 = 1.0f / l0;
    const float inv1 = 1.0f / l1;
    __half* o0 = out + (((size_t)b * Tt + t_r0) * Hh + h) * Kk;
    __half* o1 = out + (((size_t)b * Tt + t_r1) * Hh + h) * Kk;
#pragma unroll
    for (int nt = 0; nt < 16; nt++) {
        int d = nt * 8 + fc * 2;
        *(uint32_t*)(o0 + d) = h2u(__floats2half2_rn(oa[nt][0] * inv0, oa[nt][1] * inv0));
        *(uint32_t*)(o1 + d) = h2u(__floats2half2_rn(oa[nt][2] * inv1, oa[nt][3] * inv1));
    }
}

// --------------------------- launch --------------------------------------
extern "C" void kernel_launch(void* const* d_in, const int* in_sizes, int n_in,
                              void* d_out, int out_size) {
    const float* hidden  = (const float*)d_in[0];
    const float* wq      = (const float*)d_in[1];
    const float* wk      = (const float*)d_in[2];
    const float* wv      = (const float*)d_in[3];
    const float* wo      = (const float*)d_in[4];
    const float* q_scale = (const float*)d_in[5];
    const float* k_scale = (const float*)d_in[6];
    const int*   seg     = (const int*)d_in[7];
    float* out = (float*)d_out;

    float *qb, *kb;
    int* posb;
    __half *h16, *wq16, *wk16, *wv16, *wo16, *q16, *k16, *v16, *a16;
    cudaGetSymbolAddress((void**)&qb, g_q);
    cudaGetSymbolAddress((void**)&kb, g_k);
    cudaGetSymbolAddress((void**)&posb, g_pos);
    cudaGetSymbolAddress((void**)&h16, g_h16);
    cudaGetSymbolAddress((void**)&wq16, g_wq16);
    cudaGetSymbolAddress((void**)&wk16, g_wk16);
    cudaGetSymbolAddress((void**)&wv16, g_wv16);
    cudaGetSymbolAddress((void**)&wo16, g_wo16);
    cudaGetSymbolAddress((void**)&q16, g_q16);
    cudaGetSymbolAddress((void**)&k16, g_k16);
    cudaGetSymbolAddress((void**)&v16, g_v16);
    cudaGetSymbolAddress((void**)&a16, g_a16);

    // 0) convert inputs to fp16
    {
        int nh = MTOT * Dd;
        f2h_kernel<<<nh / (256 * 8), 256>>>(hidden, h16, nh);
        int nq = Dd * Hh * Kk;
        f2h_kernel<<<nq / (256 * 8), 256>>>(wq, wq16, nq);
        int nk = Dd * Gg * Kk;
        f2h_kernel<<<nk / (256 * 8), 256>>>(wk, wk16, nk);
        f2h_kernel<<<nk / (256 * 8), 256>>>(wv, wv16, nk);
        int no = Hh * Kk * Dd;
        f2h_kernel<<<no / (256 * 8), 256>>>(wo, wo16, no);
    }

    // 1) QKV projections
    {
        dim3 blk(256);
        dim3 grdQ((Hh * Kk) / 128, MTOT / 128);
        hgemm_kernel<float><<<grdQ, blk>>>(MTOT, Hh * Kk, Dd, h16, wq16, qb);
        dim3 grdK((Gg * Kk) / 128, MTOT / 128);
        hgemm_kernel<float><<<grdK, blk>>>(MTOT, Gg * Kk, Dd, h16, wk16, kb);
        hgemm_kernel<__half><<<grdK, blk>>>(MTOT, Gg * Kk, Dd, h16, wv16, v16);
    }

    // 2) positions
    pos_kernel<<<(MTOT + 255) / 256, 256>>>(seg, posb);

    // 3) RMSNorm + RoPE -> fp16 (q pre-scaled by softmax scale)
    rms_rope_kernel<<<MTOT * Hh, 128>>>(qb, q_scale, posb, q16, Hh, SOFTMAX_SCALE);
    rms_rope_kernel<<<MTOT * Gg, 128>>>(kb, k_scale, posb, k16, Gg, 1.0f);

    // 4) flash attention (fp16)
    {
        dim3 grd(Tt / 32, Gg, Bb);
        fa16_kernel<<<grd, 256>>>(q16, k16, v16, posb, a16);
    }

    // 5) output projection (f32 out)
    {
        dim3 blk(256);
        dim3 grd(Dd / 128, MTOT / 128);
        hgemm_kernel<float><<<grd, blk>>>(MTOT, Dd, Hh * Kk, a16, wo16, out);
    }
}

// round 14
// speedup vs baseline: 1.0037x; 1.0008x over previous
#include <cuda_runtime.h>
#include <cuda_fp16.h>
#include <math.h>
#include <stdint.h>

// Problem constants
#define Bb 4
#define Tt 2048
#define Dd 2048
#define Hh 16
#define Gg 4
#define Kk 128
#define Rr 4          // H / G
#define EPS 1e-6f
#define ROPE_BASE 10000.0f
#define SOFTMAX_SCALE 0.08838834764831845f  // K^-0.5

#define MTOT (Bb * Tt)          // 8192 rows

// --------------------------- scratch (device globals; no mallocs) ------------
__device__ float  g_q[(size_t)MTOT * Hh * Kk];     // 64 MB (pre-norm q, f32)
__device__ float  g_k[(size_t)MTOT * Gg * Kk];     // 16 MB (pre-norm k, f32)
__device__ int    g_pos[MTOT];
__device__ __half g_h16[(size_t)MTOT * Dd];        // 32 MB
__device__ __half g_wq16[(size_t)Dd * Hh * Kk];
__device__ __half g_wk16[(size_t)Dd * Gg * Kk];
__device__ __half g_wv16[(size_t)Dd * Gg * Kk];
__device__ __half g_wo16[(size_t)Hh * Kk * Dd];
__device__ __half g_q16[(size_t)MTOT * Hh * Kk];   // 32 MB (post norm+rope, *scale)
__device__ __half g_k16[(size_t)MTOT * Gg * Kk];   // 8 MB
__device__ __half g_v16[(size_t)MTOT * Gg * Kk];   // 8 MB (direct hgemm output)
__device__ __half g_a16[(size_t)MTOT * Hh * Kk];   // 32 MB (attn out, half)

#define MMA_F16(acc, af, b0v, b1v)                                             \
    asm volatile(                                                              \
        "mma.sync.aligned.m16n8k16.row.col.f32.f16.f16.f32 "                   \
        "{%0,%1,%2,%3}, {%4,%5,%6,%7}, {%8,%9}, {%0,%1,%2,%3};\n"              \
        : "+f"((acc)[0]), "+f"((acc)[1]), "+f"((acc)[2]), "+f"((acc)[3])       \
        : "r"((af)[0]), "r"((af)[1]), "r"((af)[2]), "r"((af)[3]),              \
          "r"(b0v), "r"(b1v))

__device__ __forceinline__ uint32_t h2u(__half2 h) { return *(uint32_t*)&h; }

// --------------------------- f32 -> f16 convert ------------------------------
__global__ __launch_bounds__(256)
void f2h_kernel(const float* __restrict__ src, __half* __restrict__ dst, int n) {
    int i = (blockIdx.x * blockDim.x + threadIdx.x) * 8;
    if (i >= n) return;
    float4 x = *(const float4*)(src + i);
    float4 y = *(const float4*)(src + i + 4);
    __half2 h0 = __floats2half2_rn(x.x, x.y);
    __half2 h1 = __floats2half2_rn(x.z, x.w);
    __half2 h2 = __floats2half2_rn(y.x, y.y);
    __half2 h3 = __floats2half2_rn(y.z, y.w);
    uint4 o;
    o.x = h2u(h0); o.y = h2u(h1); o.z = h2u(h2); o.w = h2u(h3);
    *(uint4*)(dst + i) = o;
}

// =============================================================================
// FP16 tensor-core GEMM:  C[M,N] = A[M,Kd](f16) @ B[Kd,N](f16), OutT f32/f16
// =============================================================================
#define HA_STR 40
#define HB_STR 136

template <typename OutT>
__global__ __launch_bounds__(256)
void hgemm_kernel(int M, int N, int Kd,
                  const __half* __restrict__ A,
                  const __half* __restrict__ B,
                  OutT* __restrict__ C) {
    __shared__ __half As[2][128][HA_STR];
    __shared__ __half Bs[2][32][HB_STR];

    const int tid  = threadIdx.x;
    const int lane = tid & 31;
    const int wid  = tid >> 5;
    const int warpM = wid & 1;
    const int warpN = wid >> 1;

    const __half* Ag = A + (size_t)blockIdx.y * 128 * Kd;
    const __half* Bg = B + (size_t)blockIdx.x * 128;

    float acc[4][4][4];
#pragma unroll
    for (int i = 0; i < 4; i++)
#pragma unroll
        for (int j = 0; j < 4; j++)
#pragma unroll
            for (int r = 0; r < 4; r++) acc[i][j][r] = 0.f;

    auto issue_loads = [&](int buf, int k0) {
#pragma unroll
        for (int i = 0; i < 2; i++) {
            int idx = tid + i * 256;
            int r = idx >> 2, c = (idx & 3) * 8;
            uint32_t dst = (uint32_t)__cvta_generic_to_shared(&As[buf][r][c]);
            const __half* src = Ag + (size_t)r * Kd + k0 + c;
            asm volatile("cp.async.cg.shared.global [%0], [%1], 16;\n"
                         :: "r"(dst), "l"(src));
        }
#pragma unroll
        for (int i = 0; i < 2; i++) {
            int idx = tid + i * 256;
            int r = idx >> 4, c = (idx & 15) * 8;
            uint32_t dst = (uint32_t)__cvta_generic_to_shared(&Bs[buf][r][c]);
            const __half* src = Bg + (size_t)(k0 + r) * N + c;
            asm volatile("cp.async.cg.shared.global [%0], [%1], 16;\n"
                         :: "r"(dst), "l"(src));
        }
        asm volatile("cp.async.commit_group;\n");
    };

    issue_loads(0, 0);
    const int KT = Kd >> 5;
    const int fr = lane >> 2;
    const int fc = lane & 3;
    const int grp = lane >> 3;
    const int gr8 = lane & 7;

    for (int kt = 0; kt < KT; kt++) {
        asm volatile("cp.async.wait_group 0;\n");
        __syncthreads();
        const int cur = kt & 1;
        if (kt + 1 < KT) issue_loads(cur ^ 1, (kt + 1) << 5);

#pragma unroll
        for (int kc = 0; kc < 2; kc++) {
            uint32_t af[4][4];
            uint32_t bf[4][2];
#pragma unroll
            for (int mt = 0; mt < 4; mt++) {
                int row = warpM * 64 + mt * 16 + (grp & 1) * 8 + gr8;
                int col = kc * 16 + (grp >> 1) * 8;
                uint32_t addr = (uint32_t)__cvta_generic_to_shared(&As[cur][row][col]);
                asm volatile("ldmatrix.sync.aligned.m8n8.x4.shared.b16 "
                             "{%0,%1,%2,%3}, [%4];\n"
                             : "=r"(af[mt][0]), "=r"(af[mt][1]),
                               "=r"(af[mt][2]), "=r"(af[mt][3])
                             : "r"(addr));
            }
#pragma unroll
            for (int np = 0; np < 2; np++) {
                int krow = kc * 16 + (grp & 1) * 8 + gr8;
                int ncol = warpN * 32 + np * 16 + (grp >> 1) * 8;
                uint32_t addr = (uint32_t)__cvta_generic_to_shared(&Bs[cur][krow][ncol]);
                asm volatile("ldmatrix.sync.aligned.m8n8.x4.trans.shared.b16 "
                             "{%0,%1,%2,%3}, [%4];\n"
                             : "=r"(bf[np * 2][0]), "=r"(bf[np * 2][1]),
                               "=r"(bf[np * 2 + 1][0]), "=r"(bf[np * 2 + 1][1])
                             : "r"(addr));
            }
#pragma unroll
            for (int mt = 0; mt < 4; mt++)
#pragma unroll
                for (int nt = 0; nt < 4; nt++)
                    MMA_F16(acc[mt][nt], af[mt], bf[nt][0], bf[nt][1]);
        }
        __syncthreads();
    }

    OutT* Cg = C + (size_t)blockIdx.y * 128 * N + (size_t)blockIdx.x * 128;
#pragma unroll
    for (int mt = 0; mt < 4; mt++) {
#pragma unroll
        for (int nt = 0; nt < 4; nt++) {
            int row = warpM * 64 + mt * 16 + fr;
            int col = warpN * 32 + nt * 8 + fc * 2;
            if constexpr (sizeof(OutT) == 4) {
                *(float2*)((float*)Cg + (size_t)row * N + col) =
                    make_float2(acc[mt][nt][0], acc[mt][nt][1]);
                *(float2*)((float*)Cg + (size_t)(row + 8) * N + col) =
                    make_float2(acc[mt][nt][2], acc[mt][nt][3]);
            } else {
                *(uint32_t*)((__half*)Cg + (size_t)row * N + col) =
                    h2u(__floats2half2_rn(acc[mt][nt][0], acc[mt][nt][1]));
                *(uint32_t*)((__half*)Cg + (size_t)(row + 8) * N + col) =
                    h2u(__floats2half2_rn(acc[mt][nt][2], acc[mt][nt][3]));
            }
        }
    }
}

// --------------------------- positions from sorted segment ids ---------------
__global__ void pos_kernel(const int* __restrict__ seg, int* __restrict__ pos) {
    int idx = blockIdx.x * blockDim.x + threadIdx.x;
    if (idx >= MTOT) return;
    int b = idx / Tt;
    int t = idx % Tt;
    const int* row = seg + (size_t)b * Tt;
    int s = row[t];
    int lo = 0, hi = t;
    while (lo < hi) {
        int mid = (lo + hi) >> 1;
        if (row[mid] < s) lo = mid + 1; else hi = mid;
    }
    pos[idx] = t - lo;
}

// ---------------- fused RMSNorm + RoPE, f32 in -> f16 out --------------------
__global__ __launch_bounds__(128)
void rms_rope_kernel(const float* __restrict__ x, const float* __restrict__ scale,
                     const int* __restrict__ pos, __half* __restrict__ outh,
                     int NH, float post_mul) {
    const int bt = blockIdx.x / NH;
    const int h  = blockIdx.x % NH;
    const float* p = x + ((size_t)bt * NH + h) * Kk;
    __half* po = outh + ((size_t)bt * NH + h) * Kk;

    const int i = threadIdx.x;
    float v = p[i];

    __shared__ float red[4];
    __shared__ float sx[Kk];
    float sq = v * v;
#pragma unroll
    for (int o = 16; o; o >>= 1) sq += __shfl_xor_sync(0xffffffffu, sq, o);
    if ((i & 31) == 0) red[i >> 5] = sq;
    __syncthreads();
    float var = (red[0] + red[1] + red[2] + red[3]) * (1.0f / Kk);
    float xn  = v * rsqrtf(var + EPS) * scale[i];
    sx[i] = xn;
    __syncthreads();

    if (i < Kk / 2) {
        float x1 = sx[i];
        float x2 = sx[i + Kk / 2];
        float pp = (float)pos[bt];
        float inv = expf(-logf(ROPE_BASE) * (2.0f * (float)i / (float)Kk));
        float ang = pp * inv;
        float s, c;
        sincosf(ang, &s, &c);
        po[i]           = __float2half_rn((x1 * c - x2 * s) * post_mul);
        po[i + Kk / 2]  = __float2half_rn((x2 * c + x1 * s) * post_mul);
    }
}

// =============================================================================
// Flash attention, fp16 tensor cores (m16n8k16), P kept in registers.
// Block = (32-query tile, g, b); 8 warps; warp w: head w>>1, 16 query rows.
// q is pre-scaled by SOFTMAX_SCALE. Key window [t-pos[t], t].
// =============================================================================
#define KV_STR 136

__device__ __forceinline__ float qmax2(float x) {
    x = fmaxf(x, __shfl_xor_sync(0xffffffffu, x, 1));
    x = fmaxf(x, __shfl_xor_sync(0xffffffffu, x, 2));
    return x;
}
__device__ __forceinline__ float qsum2(float x) {
    x += __shfl_xor_sync(0xffffffffu, x, 1);
    x += __shfl_xor_sync(0xffffffffu, x, 2);
    return x;
}

__global__ __launch_bounds__(256)
void fa16_kernel(const __half* __restrict__ q, const __half* __restrict__ k,
                 const __half* __restrict__ v, const int* __restrict__ pos,
                 __half* __restrict__ out) {
    __shared__ __half Ks[2][32][KV_STR];
    __shared__ __half Vs[2][32][KV_STR];

    const int tid  = threadIdx.x;
    const int lane = tid & 31;
    const int w    = tid >> 5;
    const int t0   = blockIdx.x * 32;
    const int g    = blockIdx.y;
    const int b    = blockIdx.z;

    const int h_local = w >> 1;
    const int q_base  = (w & 1) * 16;
    const int h = g * Rr + h_local;

    const int fr = lane >> 2;
    const int fc = lane & 3;

    const int t_r0 = t0 + q_base + fr;
    const int t_r1 = t_r0 + 8;
    const int w0lo = t_r0 - pos[b * Tt + t_r0];
    const int w1lo = t_r1 - pos[b * Tt + t_r1];

    // Q fragments: 8 chunks of k16
    uint32_t qf[8][4];
    {
        const __half* q0p = q + (((size_t)b * Tt + t_r0) * Hh + h) * Kk;
        const __half* q1p = q + (((size_t)b * Tt + t_r1) * Hh + h) * Kk;
#pragma unroll
        for (int kc = 0; kc < 8; kc++) {
            qf[kc][0] = *(const uint32_t*)(q0p + kc * 16 + 2 * fc);
            qf[kc][1] = *(const uint32_t*)(q1p + kc * 16 + 2 * fc);
            qf[kc][2] = *(const uint32_t*)(q0p + kc * 16 + 8 + 2 * fc);
            qf[kc][3] = *(const uint32_t*)(q1p + kc * 16 + 8 + 2 * fc);
        }
    }

    float oa[16][4];
#pragma unroll
    for (int i = 0; i < 16; i++)
#pragma unroll
        for (int j = 0; j < 4; j++) oa[i][j] = 0.f;
    float m0 = -1e30f, m1 = -1e30f, l0 = 0.f, l1 = 0.f;

    const int s_begin = (t0 - pos[b * Tt + t0]) & ~31;
    const int n_tiles = ((t0 + 31 - s_begin) >> 5) + 1;

    const __half* kg = k + ((size_t)b * Tt * Gg + g) * Kk;
    const __half* vg = v + ((size_t)b * Tt * Gg + g) * Kk;

    auto load_tile = [&](int buf, int s_tile) {
#pragma unroll
        for (int i = 0; i < 2; i++) {
            int idx = tid + i * 256;
            int r = idx >> 4, c = (idx & 15) * 8;
            uint32_t dst = (uint32_t)__cvta_generic_to_shared(&Ks[buf][r][c]);
            const __half* src = kg + (size_t)(s_tile + r) * Gg * Kk + c;
            asm volatile("cp.async.cg.shared.global [%0], [%1], 16;\n"
                         :: "r"(dst), "l"(src));
        }
#pragma unroll
        for (int i = 0; i < 2; i++) {
            int idx = tid + i * 256;
            int r = idx >> 4, c = (idx & 15) * 8;
            uint32_t dst = (uint32_t)__cvta_generic_to_shared(&Vs[buf][r][c]);
            const __half* src = vg + (size_t)(s_tile + r) * Gg * Kk + c;
            asm volatile("cp.async.cg.shared.global [%0], [%1], 16;\n"
                         :: "r"(dst), "l"(src));
        }
        asm volatile("cp.async.commit_group;\n");
    };

    load_tile(0, s_begin);

    for (int it = 0; it < n_tiles; it++) {
        const int s_tile = s_begin + it * 32;
        asm volatile("cp.async.wait_group 0;\n");
        __syncthreads();
        const int cur = it & 1;
        if (it + 1 < n_tiles) load_tile(cur ^ 1, s_tile + 32);

        // ---- scores: S[16,32] = Q @ K^T (q pre-scaled) ----
        float sc[4][4];
#pragma unroll
        for (int nt = 0; nt < 4; nt++)
#pragma unroll
            for (int i = 0; i < 4; i++) sc[nt][i] = 0.f;

#pragma unroll
        for (int nt = 0; nt < 4; nt++) {
#pragma unroll
            for (int kcp = 0; kcp < 4; kcp++) {
                uint32_t r0, r1, r2, r3;
                uint32_t addr = (uint32_t)__cvta_generic_to_shared(
                    &Ks[cur][nt * 8 + (lane & 7)][kcp * 32 + 8 * (lane >> 3)]);
                asm volatile("ldmatrix.sync.aligned.m8n8.x4.shared.b16 "
                             "{%0,%1,%2,%3}, [%4];\n"
                             : "=r"(r0), "=r"(r1), "=r"(r2), "=r"(r3)
                             : "r"(addr));
                MMA_F16(sc[nt], qf[2 * kcp], r0, r1);
                MMA_F16(sc[nt], qf[2 * kcp + 1], r2, r3);
            }
        }

        // ---- mask + online softmax ----
        float x[4][4];
        float rm0 = -1e30f, rm1 = -1e30f;
#pragma unroll
        for (int nt = 0; nt < 4; nt++) {
            int s_b = s_tile + nt * 8 + fc * 2;
            x[nt][0] = (s_b     >= w0lo && s_b     <= t_r0) ? sc[nt][0] : -1e30f;
            x[nt][1] = (s_b + 1 >= w0lo && s_b + 1 <= t_r0) ? sc[nt][1] : -1e30f;
            x[nt][2] = (s_b     >= w1lo && s_b     <= t_r1) ? sc[nt][2] : -1e30f;
            x[nt][3] = (s_b + 1 >= w1lo && s_b + 1 <= t_r1) ? sc[nt][3] : -1e30f;
            rm0 = fmaxf(rm0, fmaxf(x[nt][0], x[nt][1]));
            rm1 = fmaxf(rm1, fmaxf(x[nt][2], x[nt][3]));
        }
        rm0 = qmax2(rm0);
        rm1 = qmax2(rm1);
        const float mn0 = fmaxf(m0, rm0);
        const float mn1 = fmaxf(m1, rm1);
        const float corr0 = __expf(m0 - mn0);
        const float corr1 = __expf(m1 - mn1);

        float e[4][4];
        float rs0 = 0.f, rs1 = 0.f;
#pragma unroll
        for (int nt = 0; nt < 4; nt++) {
            e[nt][0] = (x[nt][0] > -1e29f) ? __expf(x[nt][0] - mn0) : 0.f;
            e[nt][1] = (x[nt][1] > -1e29f) ? __expf(x[nt][1] - mn0) : 0.f;
            e[nt][2] = (x[nt][2] > -1e29f) ? __expf(x[nt][2] - mn1) : 0.f;
            e[nt][3] = (x[nt][3] > -1e29f) ? __expf(x[nt][3] - mn1) : 0.f;
            rs0 += e[nt][0] + e[nt][1];
            rs1 += e[nt][2] + e[nt][3];
        }
        l0 = l0 * corr0 + qsum2(rs0);
        l1 = l1 * corr1 + qsum2(rs1);
        m0 = mn0;
        m1 = mn1;

        // ---- pack P into A fragments (registers only) ----
        uint32_t pa[2][4];
#pragma unroll
        for (int kc2 = 0; kc2 < 2; kc2++) {
            pa[kc2][0] = h2u(__floats2half2_rn(e[2 * kc2][0],     e[2 * kc2][1]));
            pa[kc2][1] = h2u(__floats2half2_rn(e[2 * kc2][2],     e[2 * kc2][3]));
            pa[kc2][2] = h2u(__floats2half2_rn(e[2 * kc2 + 1][0], e[2 * kc2 + 1][1]));
            pa[kc2][3] = h2u(__floats2half2_rn(e[2 * kc2 + 1][2], e[2 * kc2 + 1][3]));
        }

#pragma unroll
        for (int nt = 0; nt < 16; nt++) {
            oa[nt][0] *= corr0;
            oa[nt][1] *= corr0;
            oa[nt][2] *= corr1;
            oa[nt][3] *= corr1;
        }

        // ---- O += P @ V ----
#pragma unroll
        for (int nt2 = 0; nt2 < 8; nt2++) {
#pragma unroll
            for (int kc2 = 0; kc2 < 2; kc2++) {
                uint32_t r0, r1, r2, r3;
                uint32_t addr = (uint32_t)__cvta_generic_to_shared(
                    &Vs[cur][kc2 * 16 + 8 * ((lane >> 3) & 1) + (lane & 7)]
                       [nt2 * 16 + 8 * (lane >> 4)]);
                asm volatile("ldmatrix.sync.aligned.m8n8.x4.trans.shared.b16 "
                             "{%0,%1,%2,%3}, [%4];\n"
                             : "=r"(r0), "=r"(r1), "=r"(r2), "=r"(r3)
                             : "r"(addr));
                MMA_F16(oa[2 * nt2], pa[kc2], r0, r1);
                MMA_F16(oa[2 * nt2 + 1], pa[kc2], r2, r3);
            }
        }
        __syncthreads();
    }

    // ---- epilogue: write half ----
    const float inv0 = 1.0f / l0;
    const float inv1 = 1.0f / l1;
    __half* o0 = out + (((size_t)b * Tt + t_r0) * Hh + h) * Kk;
    __half* o1 = out + (((size_t)b * Tt + t_r1) * Hh + h) * Kk;
#pragma unroll
    for (int nt = 0; nt < 16; nt++) {
        int d = nt * 8 + fc * 2;
        *(uint32_t*)(o0 + d) = h2u(__floats2half2_rn(oa[nt][0] * inv0, oa[nt][1] * inv0));
        *(uint32_t*)(o1 + d) = h2u(__floats2half2_rn(oa[nt][2] * inv1, oa[nt][3] * inv1));
    }
}

// --------------------------- launch --------------------------------------
extern "C" void kernel_launch(void* const* d_in, const int* in_sizes, int n_in,
                              void* d_out, int out_size) {
    const float* hidden  = (const float*)d_in[0];
    const float* wq      = (const float*)d_in[1];
    const float* wk      = (const float*)d_in[2];
    const float* wv      = (const float*)d_in[3];
    const float* wo      = (const float*)d_in[4];
    const float* q_scale = (const float*)d_in[5];
    const float* k_scale = (const float*)d_in[6];
    const int*   seg     = (const int*)d_in[7];
    float* out = (float*)d_out;

    float *qb, *kb;
    int* posb;
    __half *h16, *wq16, *wk16, *wv16, *wo16, *q16, *k16, *v16, *a16;
    cudaGetSymbolAddress((void**)&qb, g_q);
    cudaGetSymbolAddress((void**)&kb, g_k);
    cudaGetSymbolAddress((void**)&posb, g_pos);
    cudaGetSymbolAddress((void**)&h16, g_h16);
    cudaGetSymbolAddress((void**)&wq16, g_wq16);
    cudaGetSymbolAddress((void**)&wk16, g_wk16);
    cudaGetSymbolAddress((void**)&wv16, g_wv16);
    cudaGetSymbolAddress((void**)&wo16, g_wo16);
    cudaGetSymbolAddress((void**)&q16, g_q16);
    cudaGetSymbolAddress((void**)&k16, g_k16);
    cudaGetSymbolAddress((void**)&v16, g_v16);
    cudaGetSymbolAddress((void**)&a16, g_a16);

    // 0) convert inputs to fp16
    {
        int nh = MTOT * Dd;
        f2h_kernel<<<nh / (256 * 8), 256>>>(hidden, h16, nh);
        int nq = Dd * Hh * Kk;
        f2h_kernel<<<nq / (256 * 8), 256>>>(wq, wq16, nq);
        int nk = Dd * Gg * Kk;
        f2h_kernel<<<nk / (256 * 8), 256>>>(wk, wk16, nk);
        f2h_kernel<<<nk / (256 * 8), 256>>>(wv, wv16, nk);
        int no = Hh * Kk * Dd;
        f2h_kernel<<<no / (256 * 8), 256>>>(wo, wo16, no);
    }

    // 1) QKV projections
    {
        dim3 blk(256);
        dim3 grdQ((Hh * Kk) / 128, MTOT / 128);
        hgemm_kernel<float><<<grdQ, blk>>>(MTOT, Hh * Kk, Dd, h16, wq16, qb);
        dim3 grdK((Gg * Kk) / 128, MTOT / 128);
        hgemm_kernel<float><<<grdK, blk>>>(MTOT, Gg * Kk, Dd, h16, wk16, kb);
        hgemm_kernel<__half><<<grdK, blk>>>(MTOT, Gg * Kk, Dd, h16, wv16, v16);
    }

    // 2) positions
    pos_kernel<<<(MTOT + 255) / 256, 256>>>(seg, posb);

    // 3) RMSNorm + RoPE -> fp16 (q pre-scaled by softmax scale)
    rms_rope_kernel<<<MTOT * Hh, 128>>>(qb, q_scale, posb, q16, Hh, SOFTMAX_SCALE);
    rms_rope_kernel<<<MTOT * Gg, 128>>>(kb, k_scale, posb, k16, Gg, 1.0f);

    // 4) flash attention (fp16)
    {
        dim3 grd(Tt / 32, Gg, Bb);
        fa16_kernel<<<grd, 256>>>(q16, k16, v16, posb, a16);
    }

    // 5) output projection (f32 out)
    {
        dim3 blk(256);
        dim3 grd(Dd / 128, MTOT / 128);
        hgemm_kernel<float><<<grd, blk>>>(MTOT, Dd, Hh * Kk, a16, wo16, out);
    }
}